// round 16
// baseline (speedup 1.0000x reference)
#include <cuda_runtime.h>

// Problem constants (fixed by the dataset).
#define N_NEURONS 2000000u
#define N_EDGES   16000000u

// Byte-map filter: sbyte[sj & (BSIZE-1)] != 0 <=> candidate active.
// FP rate = actives/BSIZE (~0.5%); FPs resolved by exact g_x gather in the
// second phase, so correctness never depends on the filter.
#define BSIZE 16384u                      // 16KB smem => 8 CTAs/SM

#define TCAP (1 << 20)                    // touched-list capacity
#define ACAP (1 << 20)                    // active-list capacity
#define CCAP (1 << 22)                    // candidate-edge capacity (4M)

// Scratch state (allocation-free __device__ globals; zero at load, and every
// launch restores the pristine state => deterministic graph replays).
__device__ float    g_x[N_NEURONS];
__device__ float    g_out[N_NEURONS];
__device__ unsigned g_act[ACAP];
__device__ unsigned g_acnt;
__device__ unsigned g_touched[TCAP];
__device__ unsigned g_tcnt[3];
__device__ unsigned g_cand[CCAP];         // candidate edge ids (layer-local)
__device__ unsigned g_ccnt;               // candidate count, reset after use
__device__ unsigned g_done[8];            // last-block tickets, self-resetting

// Scatter with touched-list registration. Exactly one adder per cell observes
// old == 0.0f; duplicate touched entries are defused by atomicExch in the tail.
__device__ __forceinline__ void scatter_edge(int d, float val, int r) {
    if (val == 0.0f) return;
    float old = atomicAdd(&g_out[d], val);
    if (old == 0.0f) {
        unsigned p = atomicAdd(&g_tcnt[r], 1u);
        if (p < TCAP) g_touched[p] = (unsigned)d;
    }
}

// Last-block election: true for every thread of the block that arrives last.
__device__ __forceinline__ bool elect_last_block(int which) {
    __shared__ unsigned s_last;
    __threadfence();
    __syncthreads();
    if (threadIdx.x == 0) {
        unsigned t = atomicAdd(&g_done[which], 1u);
        s_last = (t == gridDim.x - 1) ? 1u : 0u;
        if (s_last) g_done[which] = 0u;   // self-reset for next replay
    }
    __syncthreads();
    if (s_last) { __threadfence(); return true; }
    return false;
}

// Update tail: x += relu(out) over touched cells, out -> 0, new actives
// appended. atomicExch makes duplicate touched entries process exactly once.
__device__ void update_tail(int r, int tid, int nthr) {
    unsigned tc = g_tcnt[r];
    if (tc <= TCAP) {
        for (unsigned t = tid; t < tc; t += nthr) {
            unsigned i = g_touched[t];
            float v = atomicExch(&g_out[i], 0.0f);
            if (v > 0.0f) {
                float xo = g_x[i];
                g_x[i] = xo + v;
                if (xo == 0.0f) {
                    unsigned p = atomicAdd(&g_acnt, 1u);
                    if (p < ACAP) g_act[p] = i;
                }
            }
        }
    } else {                               // overflow fallback: full sweep
        for (unsigned i = tid; i < N_NEURONS; i += nthr) {
            float v = atomicExch(&g_out[i], 0.0f);
            if (v > 0.0f) {
                float xo = g_x[i];
                g_x[i] = xo + v;
                if (xo == 0.0f) {
                    unsigned p = atomicAdd(&g_acnt, 1u);
                    if (p < ACAP) g_act[p] = i;
                }
            }
        }
    }
}

// ---------------------------------------------------------------------------
// Start: seed x[0]=1, active={0}, counters=0.
// ---------------------------------------------------------------------------
__global__ void k_start() {
    g_x[0] = 1.0f;
    g_act[0] = 0u;
    g_acnt = 1u;
    g_tcnt[0] = 0u; g_tcnt[1] = 0u; g_tcnt[2] = 0u;
    g_ccnt = 0u;
    g_out[0] = 0.0f;
}

// ---------------------------------------------------------------------------
// Layer 0: active set is exactly {0, value 1.0} -> compare only (~8 hits
// total; inline gather is fine here).
// ---------------------------------------------------------------------------
__global__ void __launch_bounds__(256, 8)
k_edge_first(const int* __restrict__ src, const int* __restrict__ dst,
             const int* __restrict__ widx, const float* __restrict__ weights) {
    unsigned stride = gridDim.x * blockDim.x * 8u;
    for (unsigned i = (blockIdx.x * blockDim.x + threadIdx.x) * 8u; i < N_EDGES; i += stride) {
        int4 a = __ldcs(reinterpret_cast<const int4*>(src + i));
        int4 b = __ldcs(reinterpret_cast<const int4*>(src + i + 4));
        int s[8] = {a.x, a.y, a.z, a.w, b.x, b.y, b.z, b.w};
        #pragma unroll
        for (int j = 0; j < 8; ++j) {
            if (s[j] == 0) {
                unsigned e = i + j;
                scatter_edge(__ldg(dst + e), __ldg(weights + __ldg(widx + e)), 0);
            }
        }
    }
    if (elect_last_block(0)) update_tail(0, threadIdx.x, blockDim.x);
}

// ---------------------------------------------------------------------------
// Phase 1 (layers 1,2): SCAN ONLY. Per edge: AND + LDS.U8 + ISETP, then one
// ballot per 8-edge step; passing lanes append edge ids via warp-aggregated
// atomic. No dependent gather, no scatter, no divergence in the stream loop.
// Uniform trip count keeps ballots converged; tail lanes fold validity in.
// ---------------------------------------------------------------------------
__global__ void __launch_bounds__(256, 8)
k_scan(const int* __restrict__ src, int done_slot) {
    __shared__ unsigned char sbyte[BSIZE];

    {   // zero + build the byte map
        uint4* p = reinterpret_cast<uint4*>(sbyte);
        const uint4 z = make_uint4(0u, 0u, 0u, 0u);
        for (unsigned t = threadIdx.x; t < BSIZE / 16u; t += blockDim.x) p[t] = z;
    }
    __syncthreads();
    unsigned cnt = g_acnt;
    if (cnt > ACAP) cnt = ACAP;
    for (unsigned t = threadIdx.x; t < cnt; t += blockDim.x)
        sbyte[g_act[t] & (BSIZE - 1u)] = 1u;
    __syncthreads();

    const unsigned lane = threadIdx.x & 31u;
    const unsigned lmlt = (1u << lane) - 1u;          // lanemask_lt
    const unsigned stride = gridDim.x * blockDim.x * 8u;
    const unsigned start = (blockIdx.x * blockDim.x + threadIdx.x) * 8u;
    const int NITER = (int)((N_EDGES + stride - 1) / stride);   // uniform

    for (int it = 0; it < NITER; ++it) {
        unsigned i = start + (unsigned)it * stride;
        bool valid = (i < N_EDGES);
        int4 a = valid ? __ldcs(reinterpret_cast<const int4*>(src + i))
                       : make_int4(-1, -1, -1, -1);
        int4 b = valid ? __ldcs(reinterpret_cast<const int4*>(src + i + 4))
                       : make_int4(-1, -1, -1, -1);
        int s[8] = {a.x, a.y, a.z, a.w, b.x, b.y, b.z, b.w};
        #pragma unroll
        for (int j = 0; j < 8; ++j) {
            bool pass = valid && sbyte[((unsigned)s[j]) & (BSIZE - 1u)];
            unsigned bal = __ballot_sync(0xFFFFFFFFu, pass);
            if (bal) {
                int leader = __ffs(bal) - 1;
                unsigned base = 0u;
                if ((int)lane == leader) base = atomicAdd(&g_ccnt, (unsigned)__popc(bal));
                base = __shfl_sync(0xFFFFFFFFu, base, leader);
                if (pass) {
                    unsigned p = base + (unsigned)__popc(bal & lmlt);
                    if (p < CCAP) g_cand[p] = i + (unsigned)j;
                }
            }
        }
    }
    // no tail work: candidate list is consumed by k_gather
    (void)done_slot;
}

// ---------------------------------------------------------------------------
// Phase 2: process candidates exactly. FPs read g_x == 0 and drop out. If the
// candidate list overflowed, rescan all edges directly (slow but correct).
// Tail: run the round's update and reset the candidate counter.
// ---------------------------------------------------------------------------
__global__ void __launch_bounds__(256, 8)
k_gather(const int* __restrict__ src, const int* __restrict__ dst,
         const int* __restrict__ widx, const float* __restrict__ weights,
         int round, int done_slot) {
    unsigned tc = g_ccnt;
    unsigned nthr = gridDim.x * blockDim.x;
    unsigned tid = blockIdx.x * blockDim.x + threadIdx.x;
    if (tc <= CCAP) {
        for (unsigned t = tid; t < tc; t += nthr) {
            unsigned e = g_cand[t];
            float xv = g_x[(unsigned)__ldg(src + e)];
            if (xv != 0.0f)
                scatter_edge(__ldg(dst + e), xv * __ldg(weights + __ldg(widx + e)), round);
        }
    } else {                                 // overflow: full direct rescan
        for (unsigned e = tid; e < N_EDGES; e += nthr) {
            float xv = g_x[(unsigned)__ldg(src + e)];
            if (xv != 0.0f)
                scatter_edge(__ldg(dst + e), xv * __ldg(weights + __ldg(widx + e)), round);
        }
    }
    if (elect_last_block(done_slot)) {
        update_tail(round, threadIdx.x, blockDim.x);
        if (threadIdx.x == 0) g_ccnt = 0u;   // ready for next scan / replay
    }
}

// ---------------------------------------------------------------------------
// Layer 3: only out[0] matters -> scan dst==0, gather x[src] on the ~8 hits.
// Tail writes the final result and restores pristine global state.
// ---------------------------------------------------------------------------
__global__ void __launch_bounds__(256, 8)
k_edge_last(const int* __restrict__ src, const int* __restrict__ dst,
            const int* __restrict__ widx, const float* __restrict__ weights,
            float* __restrict__ out) {
    unsigned stride = gridDim.x * blockDim.x * 8u;
    for (unsigned i = (blockIdx.x * blockDim.x + threadIdx.x) * 8u; i < N_EDGES; i += stride) {
        int4 a = __ldcs(reinterpret_cast<const int4*>(dst + i));
        int4 b = __ldcs(reinterpret_cast<const int4*>(dst + i + 4));
        int d[8] = {a.x, a.y, a.z, a.w, b.x, b.y, b.z, b.w};
        #pragma unroll
        for (int j = 0; j < 8; ++j) {
            if (d[j] == 0) {
                unsigned e = i + j;
                atomicAdd(&g_out[0], g_x[__ldg(src + e)] * __ldg(weights + __ldg(widx + e)));
            }
        }
    }
    if (elect_last_block(3)) {
        int tid = threadIdx.x, nthr = blockDim.x;
        if (tid == 0) out[0] = g_x[0] + fmaxf(g_out[0], 0.0f);
        // Cleanup: zero every nonzero g_x cell (active list), zero g_out[0].
        unsigned ac = g_acnt;
        if (ac <= ACAP) {
            for (unsigned t = tid; t < ac; t += nthr) g_x[g_act[t]] = 0.0f;
        } else {
            for (unsigned i = tid; i < N_NEURONS; i += nthr) g_x[i] = 0.0f;
        }
        if (tid == 0) g_out[0] = 0.0f;
    }
}

// ---------------------------------------------------------------------------
// Launch sequence (graph-capturable: kernel launches only). Per-layer edge
// pointers pre-offset on the host so device indexing stays 32-bit.
// Inputs: [0]=weights f32[1024], [1]=src i32[4*16M], [2]=dst i32[4*16M],
// [3]=widx i32[4*16M]. Output: f32[1].
// ---------------------------------------------------------------------------
extern "C" void kernel_launch(void* const* d_in, const int* in_sizes, int n_in,
                              void* d_out, int out_size) {
    const float* weights = (const float*)d_in[0];
    const int*   src     = (const int*)d_in[1];
    const int*   dst     = (const int*)d_in[2];
    const int*   widx    = (const int*)d_in[3];
    float*       out     = (float*)d_out;

    const int EB = 1184, ET = 256;   // 8 CTAs/SM on 148 SMs
    const size_t E = (size_t)N_EDGES;

    k_start<<<1, 1>>>();
    k_edge_first<<<EB, ET>>>(src, dst, widx, weights);
    k_scan<<<EB, ET>>>(src + E, 4);
    k_gather<<<EB, ET>>>(src + E, dst + E, widx + E, weights, 1, 5);
    k_scan<<<EB, ET>>>(src + 2*E, 6);
    k_gather<<<EB, ET>>>(src + 2*E, dst + 2*E, widx + 2*E, weights, 2, 7);
    k_edge_last<<<EB, ET>>>(src + 3*E, dst + 3*E, widx + 3*E, weights, out);
}

// round 17
// speedup vs baseline: 1.3205x; 1.3205x over previous
#include <cuda_runtime.h>

// Problem constants (fixed by the dataset).
#define N_NEURONS 2000000u
#define N_EDGES   16000000u

// Byte-map filter: sbyte[sj & (BSIZE-1)] != 0 <=> candidate active.
// FP rate = actives/BSIZE (~0.5%); FPs resolved by an exact g_x gather, so
// correctness never depends on the filter. No false negatives possible.
#define BSIZE 16384u                      // 16KB smem => 8 CTAs/SM

#define TCAP (1 << 20)                    // touched-list capacity
#define ACAP (1 << 20)                    // active-list capacity

// Scratch state (allocation-free __device__ globals; zero at load, and every
// launch restores the pristine state => deterministic graph replays).
__device__ float    g_x[N_NEURONS];
__device__ float    g_out[N_NEURONS];
__device__ unsigned g_act[ACAP];
__device__ unsigned g_acnt;
__device__ unsigned g_touched[TCAP];
__device__ unsigned g_tcnt[3];
__device__ unsigned g_done[4];            // last-block tickets, self-resetting

// Scatter with touched-list registration. Exactly one adder per cell observes
// old == 0.0f; duplicate touched entries are defused by atomicExch in the tail.
__device__ __forceinline__ void scatter_edge(int d, float val, int r) {
    if (val == 0.0f) return;
    float old = atomicAdd(&g_out[d], val);
    if (old == 0.0f) {
        unsigned p = atomicAdd(&g_tcnt[r], 1u);
        if (p < TCAP) g_touched[p] = (unsigned)d;
    }
}

// Last-block election: true for every thread of the block that arrives last.
__device__ __forceinline__ bool elect_last_block(int which) {
    __shared__ unsigned s_last;
    __threadfence();
    __syncthreads();
    if (threadIdx.x == 0) {
        unsigned t = atomicAdd(&g_done[which], 1u);
        s_last = (t == gridDim.x - 1) ? 1u : 0u;
        if (s_last) g_done[which] = 0u;   // self-reset for next replay
    }
    __syncthreads();
    if (s_last) { __threadfence(); return true; }
    return false;
}

// Update tail: x += relu(out) over touched cells, out -> 0, new actives
// appended. atomicExch makes duplicate touched entries process exactly once.
__device__ void update_tail(int r, int tid, int nthr) {
    unsigned tc = g_tcnt[r];
    if (tc <= TCAP) {
        for (unsigned t = tid; t < tc; t += nthr) {
            unsigned i = g_touched[t];
            float v = atomicExch(&g_out[i], 0.0f);
            if (v > 0.0f) {
                float xo = g_x[i];
                g_x[i] = xo + v;
                if (xo == 0.0f) {
                    unsigned p = atomicAdd(&g_acnt, 1u);
                    if (p < ACAP) g_act[p] = i;
                }
            }
        }
    } else {                               // overflow fallback: full sweep
        for (unsigned i = tid; i < N_NEURONS; i += nthr) {
            float v = atomicExch(&g_out[i], 0.0f);
            if (v > 0.0f) {
                float xo = g_x[i];
                g_x[i] = xo + v;
                if (xo == 0.0f) {
                    unsigned p = atomicAdd(&g_acnt, 1u);
                    if (p < ACAP) g_act[p] = i;
                }
            }
        }
    }
}

// ---------------------------------------------------------------------------
// Start: seed x[0]=1, active={0}, counters=0.
// ---------------------------------------------------------------------------
__global__ void k_start() {
    g_x[0] = 1.0f;
    g_act[0] = 0u;
    g_acnt = 1u;
    g_tcnt[0] = 0u; g_tcnt[1] = 0u; g_tcnt[2] = 0u;
    g_out[0] = 0.0f;
}

// ---------------------------------------------------------------------------
// Layer 0: active set is exactly {0, value 1.0} -> compare only. No LDS in
// the chain (2 LDG = 2 scoreboard slots); proven ~10.5us. Unchanged control.
// ---------------------------------------------------------------------------
__global__ void __launch_bounds__(256, 8)
k_edge_first(const int* __restrict__ src, const int* __restrict__ dst,
             const int* __restrict__ widx, const float* __restrict__ weights) {
    unsigned stride = gridDim.x * blockDim.x * 8u;
    for (unsigned i = (blockIdx.x * blockDim.x + threadIdx.x) * 8u; i < N_EDGES; i += stride) {
        int4 a = __ldcs(reinterpret_cast<const int4*>(src + i));
        int4 b = __ldcs(reinterpret_cast<const int4*>(src + i + 4));
        int s[8] = {a.x, a.y, a.z, a.w, b.x, b.y, b.z, b.w};
        #pragma unroll
        for (int j = 0; j < 8; ++j) {
            if (s[j] == 0) {
                unsigned e = i + j;
                scatter_edge(__ldg(dst + e), __ldg(weights + __ldg(widx + e)), 0);
            }
        }
    }
    if (elect_last_block(0)) update_tail(0, threadIdx.x, blockDim.x);
}

// ---------------------------------------------------------------------------
// Layers 1,2: byte-map filter at UNROLL 4 — exactly 1 LDG.128 + 4 LDS.U8
// outstanding per iteration = 5 var-lat ops <= 6 HW scoreboard slots, so each
// load gets its own slot and no wait drains unrelated loads. Test per edge:
// AND + LDS.U8 + ISETP. Pass (hit or ~0.5% FP) -> exact g_x gather.
// ---------------------------------------------------------------------------
__global__ void __launch_bounds__(256, 8)
k_edge_bfilt(const int* __restrict__ src, const int* __restrict__ dst,
             const int* __restrict__ widx, const float* __restrict__ weights,
             int round) {
    __shared__ unsigned char sbyte[BSIZE];

    // Zero the byte map (16KB) with wide stores.
    {
        uint4* p = reinterpret_cast<uint4*>(sbyte);
        const uint4 z = make_uint4(0u, 0u, 0u, 0u);
        for (unsigned t = threadIdx.x; t < BSIZE / 16u; t += blockDim.x) p[t] = z;
    }
    __syncthreads();

    // Mark active keys (same-value write races are benign).
    unsigned cnt = g_acnt;
    if (cnt > ACAP) cnt = ACAP;
    for (unsigned t = threadIdx.x; t < cnt; t += blockDim.x)
        sbyte[g_act[t] & (BSIZE - 1u)] = 1u;
    __syncthreads();

    const unsigned stride = gridDim.x * blockDim.x * 4u;
    for (unsigned i = (blockIdx.x * blockDim.x + threadIdx.x) * 4u; i < N_EDGES; i += stride) {
        int4 a = __ldcs(reinterpret_cast<const int4*>(src + i));
        unsigned s0 = (unsigned)a.x, s1 = (unsigned)a.y;
        unsigned s2 = (unsigned)a.z, s3 = (unsigned)a.w;
        unsigned char f0 = sbyte[s0 & (BSIZE - 1u)];
        unsigned char f1 = sbyte[s1 & (BSIZE - 1u)];
        unsigned char f2 = sbyte[s2 & (BSIZE - 1u)];
        unsigned char f3 = sbyte[s3 & (BSIZE - 1u)];
        if (f0) { float xv = g_x[s0]; if (xv != 0.0f)
            scatter_edge(__ldg(dst + i),     xv * __ldg(weights + __ldg(widx + i)),     round); }
        if (f1) { float xv = g_x[s1]; if (xv != 0.0f)
            scatter_edge(__ldg(dst + i + 1), xv * __ldg(weights + __ldg(widx + i + 1)), round); }
        if (f2) { float xv = g_x[s2]; if (xv != 0.0f)
            scatter_edge(__ldg(dst + i + 2), xv * __ldg(weights + __ldg(widx + i + 2)), round); }
        if (f3) { float xv = g_x[s3]; if (xv != 0.0f)
            scatter_edge(__ldg(dst + i + 3), xv * __ldg(weights + __ldg(widx + i + 3)), round); }
    }
    if (elect_last_block(round)) update_tail(round, threadIdx.x, blockDim.x);
}

// ---------------------------------------------------------------------------
// Layer 3: only out[0] matters -> scan dst==0, gather x[src] on the ~8 hits.
// Tail writes the final result and restores pristine global state. Unchanged
// control (no LDS; ~10.5us).
// ---------------------------------------------------------------------------
__global__ void __launch_bounds__(256, 8)
k_edge_last(const int* __restrict__ src, const int* __restrict__ dst,
            const int* __restrict__ widx, const float* __restrict__ weights,
            float* __restrict__ out) {
    unsigned stride = gridDim.x * blockDim.x * 8u;
    for (unsigned i = (blockIdx.x * blockDim.x + threadIdx.x) * 8u; i < N_EDGES; i += stride) {
        int4 a = __ldcs(reinterpret_cast<const int4*>(dst + i));
        int4 b = __ldcs(reinterpret_cast<const int4*>(dst + i + 4));
        int d[8] = {a.x, a.y, a.z, a.w, b.x, b.y, b.z, b.w};
        #pragma unroll
        for (int j = 0; j < 8; ++j) {
            if (d[j] == 0) {
                unsigned e = i + j;
                atomicAdd(&g_out[0], g_x[__ldg(src + e)] * __ldg(weights + __ldg(widx + e)));
            }
        }
    }
    if (elect_last_block(3)) {
        int tid = threadIdx.x, nthr = blockDim.x;
        if (tid == 0) out[0] = g_x[0] + fmaxf(g_out[0], 0.0f);
        // Cleanup: zero every nonzero g_x cell (active list), zero g_out[0].
        unsigned ac = g_acnt;
        if (ac <= ACAP) {
            for (unsigned t = tid; t < ac; t += nthr) g_x[g_act[t]] = 0.0f;
        } else {
            for (unsigned i = tid; i < N_NEURONS; i += nthr) g_x[i] = 0.0f;
        }
        if (tid == 0) g_out[0] = 0.0f;
    }
}

// ---------------------------------------------------------------------------
// Launch sequence (graph-capturable: kernel launches only). Per-layer edge
// pointers pre-offset on the host so device indexing stays 32-bit.
// Inputs: [0]=weights f32[1024], [1]=src i32[4*16M], [2]=dst i32[4*16M],
// [3]=widx i32[4*16M]. Output: f32[1].
// ---------------------------------------------------------------------------
extern "C" void kernel_launch(void* const* d_in, const int* in_sizes, int n_in,
                              void* d_out, int out_size) {
    const float* weights = (const float*)d_in[0];
    const int*   src     = (const int*)d_in[1];
    const int*   dst     = (const int*)d_in[2];
    const int*   widx    = (const int*)d_in[3];
    float*       out     = (float*)d_out;

    const int EB = 1184, ET = 256;   // 8 CTAs/SM on 148 SMs
    const size_t E = (size_t)N_EDGES;

    k_start<<<1, 1>>>();
    k_edge_first<<<EB, ET>>>(src, dst, widx, weights);
    k_edge_bfilt<<<EB, ET>>>(src + E,   dst + E,   widx + E,   weights, 1);
    k_edge_bfilt<<<EB, ET>>>(src + 2*E, dst + 2*E, widx + 2*E, weights, 2);
    k_edge_last<<<EB, ET>>>(src + 3*E, dst + 3*E, widx + 3*E, weights, out);
}